// round 8
// baseline (speedup 1.0000x reference)
#include <cuda_runtime.h>
#include <cuda_bf16.h>
#include <cstdint>

#define NROWS 16384
#define CDIM  256
#define KEMB  8192
#define NBATCH 16
#define HW    1024
#define OUT_N (NBATCH * CDIM * HW)   // 4194304

#define NTILES 64                     // 8192 / 128 column tiles
#define MARGIN 4.0e-4f

#define AP    272                     // int8 smem row pitch (256 + 16 pad)
#define ABUFI (128 * AP)              // 34816 B per operand tile
#define SCOFF (2 * ABUFI)             // scale stage offset
#define GEMM_SMEM (2 * ABUFI + 1024)  // 70656 B -> 2 CTAs/SM
#define RPW 17                        // reduction smem pitch (words)

// ---------------- static device scratch ----------------
__device__ float   g_xt[NROWS * CDIM];    // z transposed [n][c] fp32
__device__ int8_t  g_xq[NROWS * CDIM];    // int8 quantized x
__device__ int8_t  g_eq[KEMB * CDIM];     // int8 quantized emb
__device__ float   g_sx[NROWS];           // x row scales (absmax/127)
__device__ float   g_se[KEMB];            // emb row scales
__device__ float   g_rownorm[NROWS];
__device__ int     g_idx[NROWS];
__device__ double  g_partial[4096];
__device__ float4  g_tv[NROWS * NTILES];  // top-4 coarse (-2*dot) per (row,tile)
__device__ int4    g_ti[NROWS * NTILES];  // matching indices

// top-4 running insert, strict < (keeps earliest-seen on ties)
#define TOP4_INSERT(dv, j)                                                    \
    if ((dv) < v3) {                                                          \
        if ((dv) < v2) {                                                      \
            v3 = v2; i3 = i2;                                                 \
            if ((dv) < v1) {                                                  \
                v2 = v1; i2 = i1;                                             \
                if ((dv) < v0) { v1 = v0; i1 = i0; v0 = (dv); i0 = (j); }     \
                else           { v1 = (dv); i1 = (j); }                       \
            } else { v2 = (dv); i2 = (j); }                                   \
        } else { v3 = (dv); i3 = (j); }                                       \
    }

__device__ __forceinline__ uint32_t smem_u32(const void* p) {
    uint32_t a;
    asm("{ .reg .u64 t; cvta.to.shared.u64 t, %1; cvt.u32.u64 %0, t; }" : "=r"(a) : "l"(p));
    return a;
}
__device__ __forceinline__ void ldsm_x4(uint32_t& r0, uint32_t& r1, uint32_t& r2,
                                        uint32_t& r3, uint32_t addr) {
    asm volatile("ldmatrix.sync.aligned.m8n8.x4.shared.b16 {%0,%1,%2,%3}, [%4];"
                 : "=r"(r0), "=r"(r1), "=r"(r2), "=r"(r3) : "r"(addr));
}
#define CP16(dst, src) \
    asm volatile("cp.async.cg.shared.global [%0], [%1], 16;" :: "r"(dst), "l"(src))
#define CP_COMMIT() asm volatile("cp.async.commit_group;" ::: "memory")

// ---------------- K0: transpose z[B,C,HW] -> g_xt ----------------
__global__ void k_transpose(const float* __restrict__ z) {
    __shared__ float t[32][33];
    int b = blockIdx.z, c0 = blockIdx.y * 32, hw0 = blockIdx.x * 32;
    int tx = threadIdx.x, ty = threadIdx.y;        // (32, 8)
    #pragma unroll
    for (int i = ty; i < 32; i += 8)
        t[i][tx] = z[((size_t)(b * CDIM + c0 + i)) * HW + hw0 + tx];
    __syncthreads();
    #pragma unroll
    for (int i = ty; i < 32; i += 8)
        g_xt[((size_t)(b * HW + hw0 + i)) * CDIM + c0 + tx] = t[tx][i];
}

// ---------------- K1: per-row |x|^2 + absmax + int8 quantize ----------------
__global__ void k_rowprep() {
    int row  = blockIdx.x * 8 + threadIdx.y;       // (32, 8)
    int lane = threadIdx.x;
    const float* r = g_xt + (size_t)row * CDIM;
    double acc = 0.0;
    float amax = 0.0f;
    float4 vv[2];
    #pragma unroll
    for (int h = 0; h < 2; h++) {
        float4 v = *reinterpret_cast<const float4*>(&r[h * 128 + lane * 4]);
        vv[h] = v;
        acc += (double)__fmul_rn(v.x, v.x);
        acc += (double)__fmul_rn(v.y, v.y);
        acc += (double)__fmul_rn(v.z, v.z);
        acc += (double)__fmul_rn(v.w, v.w);
        amax = fmaxf(amax, fmaxf(fmaxf(fabsf(v.x), fabsf(v.y)),
                                 fmaxf(fabsf(v.z), fabsf(v.w))));
    }
    #pragma unroll
    for (int off = 16; off > 0; off >>= 1) {
        acc += __shfl_down_sync(0xffffffffu, acc, off);
        amax = fmaxf(amax, __shfl_xor_sync(0xffffffffu, amax, off));
    }
    float inv = (amax > 0.0f) ? (127.0f / amax) : 0.0f;
    #pragma unroll
    for (int h = 0; h < 2; h++) {
        char4 q;
        q.x = (char)__float2int_rn(vv[h].x * inv);
        q.y = (char)__float2int_rn(vv[h].y * inv);
        q.z = (char)__float2int_rn(vv[h].z * inv);
        q.w = (char)__float2int_rn(vv[h].w * inv);
        *reinterpret_cast<char4*>(g_xq + (size_t)row * CDIM + h * 128 + lane * 4) = q;
    }
    if (lane == 0) {
        g_rownorm[row] = (float)acc;
        g_sx[row] = amax * (1.0f / 127.0f);
    }
}

// ---------------- K1b: per-codeword absmax + int8 quantize ----------------
__global__ void k_eprep(const float* __restrict__ emb) {
    int row  = blockIdx.x * 8 + threadIdx.y;       // (32, 8)
    int lane = threadIdx.x;
    const float* r = emb + (size_t)row * CDIM;
    float amax = 0.0f;
    float4 vv[2];
    #pragma unroll
    for (int h = 0; h < 2; h++) {
        float4 v = *reinterpret_cast<const float4*>(&r[h * 128 + lane * 4]);
        vv[h] = v;
        amax = fmaxf(amax, fmaxf(fmaxf(fabsf(v.x), fabsf(v.y)),
                                 fmaxf(fabsf(v.z), fabsf(v.w))));
    }
    #pragma unroll
    for (int off = 16; off > 0; off >>= 1)
        amax = fmaxf(amax, __shfl_xor_sync(0xffffffffu, amax, off));
    float inv = (amax > 0.0f) ? (127.0f / amax) : 0.0f;
    #pragma unroll
    for (int h = 0; h < 2; h++) {
        char4 q;
        q.x = (char)__float2int_rn(vv[h].x * inv);
        q.y = (char)__float2int_rn(vv[h].y * inv);
        q.z = (char)__float2int_rn(vv[h].z * inv);
        q.w = (char)__float2int_rn(vv[h].w * inv);
        *reinterpret_cast<char4*>(g_eq + (size_t)row * CDIM + h * 128 + lane * 4) = q;
    }
    if (lane == 0) g_se[row] = amax * (1.0f / 127.0f);
}

// ---------------- K2: coarse int8 IMMA GEMM + per-tile top-4 ----------------
// CTA: 128 rows x 128 cols, FULL K=256 int8 resident (A 34KB + B 34KB).
// 512 thr = 16 warps (4m x 4n), warp tile 32x32, 8 k-steps of k32.
__global__ __launch_bounds__(512, 2) void k_gemm_coarse() {
    extern __shared__ __align__(16) char smem[];
    const uint32_t sbase = smem_u32(smem);
    const int tid = threadIdx.x;
    const int rowBase = blockIdx.x * 128;
    const int colBase = blockIdx.y * 128;

    float* ssx = reinterpret_cast<float*>(smem + SCOFF);
    float* sse = ssx + 128;
    if (tid < 128)      ssx[tid] = g_sx[rowBase + tid];
    else if (tid < 256) sse[tid - 128] = g_se[colBase + tid - 128];

    // ---- load A+B tiles (64KB) via cp.async ----
    {
        const char* Ag = (const char*)(g_xq + (size_t)rowBase * CDIM);
        const char* Bg = (const char*)(g_eq + (size_t)colBase * CDIM);
        #pragma unroll
        for (int it = 0; it < 4; it++) {
            int t = tid + it * 512;                // 2048 16B chunks per operand
            int r = t >> 4, c = t & 15;
            uint32_t so = (uint32_t)(r * AP + c * 16);
            size_t  go = (size_t)r * CDIM + c * 16;
            CP16(sbase + so, Ag + go);
            CP16(sbase + ABUFI + so, Bg + go);
        }
        CP_COMMIT();
    }

    const int lane = tid & 31, wid = tid >> 5;
    const int g = lane >> 2, m4 = lane & 3;
    const int mw = wid >> 2, nw = wid & 3;

    int c[2][4][4];
    #pragma unroll
    for (int mt = 0; mt < 2; mt++)
        #pragma unroll
        for (int nt = 0; nt < 4; nt++)
            #pragma unroll
            for (int q = 0; q < 4; q++) c[mt][nt][q] = 0;

    // ldmatrix per-lane base addresses (same tile scheme as bf16, int8 pitch)
    const uint32_t bA = sbase + (uint32_t)((mw * 32 + (lane & 15)) * AP
                                           + ((lane >> 4) & 1) * 16);
    const uint32_t bB = sbase + ABUFI
                      + (uint32_t)((nw * 32 + ((lane >> 4) & 1) * 8 + (lane & 7)) * AP
                                   + ((lane >> 3) & 1) * 16);

    asm volatile("cp.async.wait_group 0;" ::: "memory");
    __syncthreads();

    #pragma unroll
    for (int ks = 0; ks < 8; ks++) {
        const uint32_t ko = ks * 32;               // 32 int8 = 32 bytes
        uint32_t a[2][4], b[2][4];
        ldsm_x4(a[0][0], a[0][1], a[0][2], a[0][3], bA + ko);
        ldsm_x4(a[1][0], a[1][1], a[1][2], a[1][3], bA + 16 * AP + ko);
        ldsm_x4(b[0][0], b[0][1], b[0][2], b[0][3], bB + ko);
        ldsm_x4(b[1][0], b[1][1], b[1][2], b[1][3], bB + 16 * AP + ko);
        #pragma unroll
        for (int mt = 0; mt < 2; mt++)
            #pragma unroll
            for (int ntp = 0; ntp < 2; ntp++) {
                asm volatile(
                    "mma.sync.aligned.m16n8k32.row.col.s32.s8.s8.s32 "
                    "{%0,%1,%2,%3}, {%4,%5,%6,%7}, {%8,%9}, {%0,%1,%2,%3};"
                    : "+r"(c[mt][ntp*2][0]), "+r"(c[mt][ntp*2][1]),
                      "+r"(c[mt][ntp*2][2]), "+r"(c[mt][ntp*2][3])
                    : "r"(a[mt][0]), "r"(a[mt][1]), "r"(a[mt][2]), "r"(a[mt][3]),
                      "r"(b[0+ntp][0]), "r"(b[0+ntp][1]));
                asm volatile(
                    "mma.sync.aligned.m16n8k32.row.col.s32.s8.s8.s32 "
                    "{%0,%1,%2,%3}, {%4,%5,%6,%7}, {%8,%9}, {%0,%1,%2,%3};"
                    : "+r"(c[mt][ntp*2+1][0]), "+r"(c[mt][ntp*2+1][1]),
                      "+r"(c[mt][ntp*2+1][2]), "+r"(c[mt][ntp*2+1][3])
                    : "r"(a[mt][0]), "r"(a[mt][1]), "r"(a[mt][2]), "r"(a[mt][3]),
                      "r"(b[0+ntp][2]), "r"(b[0+ntp][3]));
            }
    }
    // NOTE on b indexing: for ntp=0, regs b[0][0..1]=(n0-7,k0/k16)?  Layout per
    // ldsm tiles: b[x][0]=n0-7 kLo, b[x][1]=n0-7 kHi, b[x][2]=n8-15 kLo, b[x][3]=n8-15 kHi
    // with x selecting the 16-n group. The two MMAs above consume (b[x][0],b[x][1])
    // and (b[x][2],b[x][3]) -> n-tiles ntp*2 and ntp*2+1. Columns: nt*8 groups.
    __syncthreads();   // tiles dead; reuse smem for reduction

    float* redv = reinterpret_cast<float*>(smem);
    int*   redi = reinterpret_cast<int*>(smem) + 128 * RPW;

    // ---- register epilogue: dv = -2*sx*se*dot, per-thread top-4, quad merge ----
    #pragma unroll
    for (int lr = 0; lr < 4; lr++) {
        const int mt = lr >> 1, hf = lr & 1;
        const int row = mw * 32 + mt * 16 + hf * 8 + g;
        const float sc = -2.0f * ssx[row];
        float v0 = 1e30f, v1 = 1e30f, v2 = 1e30f, v3 = 1e30f;
        int   i0 = 0,     i1 = 0,     i2 = 0,     i3 = 0;
        #pragma unroll
        for (int nt = 0; nt < 4; nt++)
            #pragma unroll
            for (int e = 0; e < 2; e++) {
                int jl = nw * 32 + nt * 8 + m4 * 2 + e;
                float dv = sc * sse[jl] * (float)c[mt][nt][hf * 2 + e];
                int j = colBase + jl;
                TOP4_INSERT(dv, j);
            }
        #pragma unroll
        for (int s = 1; s <= 2; s <<= 1) {
            float w0 = __shfl_xor_sync(0xffffffffu, v0, s);
            float w1 = __shfl_xor_sync(0xffffffffu, v1, s);
            float w2 = __shfl_xor_sync(0xffffffffu, v2, s);
            float w3 = __shfl_xor_sync(0xffffffffu, v3, s);
            int   q0 = __shfl_xor_sync(0xffffffffu, i0, s);
            int   q1 = __shfl_xor_sync(0xffffffffu, i1, s);
            int   q2 = __shfl_xor_sync(0xffffffffu, i2, s);
            int   q3 = __shfl_xor_sync(0xffffffffu, i3, s);
            TOP4_INSERT(w0, q0); TOP4_INSERT(w1, q1);
            TOP4_INSERT(w2, q2); TOP4_INSERT(w3, q3);
        }
        if (m4 == 0) {
            int base = row * RPW + nw * 4;
            redv[base + 0] = v0; redv[base + 1] = v1;
            redv[base + 2] = v2; redv[base + 3] = v3;
            redi[base + 0] = i0; redi[base + 1] = i1;
            redi[base + 2] = i2; redi[base + 3] = i3;
        }
    }
    __syncthreads();

    // ---- merge 4 warp-column ranges -> per-row top-4 over 128 cols ----
    if (tid < 128) {
        float v0 = 1e30f, v1 = 1e30f, v2 = 1e30f, v3 = 1e30f;
        int   i0 = 0,     i1 = 0,     i2 = 0,     i3 = 0;
        #pragma unroll
        for (int e = 0; e < 16; e++) {
            float dv = redv[tid * RPW + e];
            int j = redi[tid * RPW + e];
            TOP4_INSERT(dv, j);
        }
        int n = rowBase + tid;
        g_tv[(size_t)n * NTILES + blockIdx.y] = make_float4(v0, v1, v2, v3);
        g_ti[(size_t)n * NTILES + blockIdx.y] = make_int4(i0, i1, i2, i3);
    }
}

// ---------------- K3: exact rescore of near-min candidates ----------------
// One warp per row; 256 stored entries; rescore all within MARGIN of coarse min
// with the EXACT fp32 chain; lexicographic (d, j) = first-index tie-break.
__global__ __launch_bounds__(128) void k_rescore(const float* __restrict__ emb,
                                                 float* __restrict__ idx_out_f) {
    int wid = threadIdx.x >> 5, lid = threadIdx.x & 31;
    int n = blockIdx.x * 4 + wid;
    const float4* tv = g_tv + (size_t)n * NTILES;
    const int4*   ti = g_ti + (size_t)n * NTILES;

    float ev[8]; int ei[8];
    #pragma unroll
    for (int q = 0; q < 8; q++) {
        int e = q * 32 + lid;                      // entry 0..255
        float4 v4 = tv[e >> 2];
        int4   i4 = ti[e >> 2];
        int rk = e & 3;
        ev[q] = (rk == 0) ? v4.x : (rk == 1) ? v4.y : (rk == 2) ? v4.z : v4.w;
        ei[q] = (rk == 0) ? i4.x : (rk == 1) ? i4.y : (rk == 2) ? i4.z : i4.w;
    }
    float m = 1e30f;
    #pragma unroll
    for (int q = 0; q < 8; q++) m = fminf(m, ev[q]);
    #pragma unroll
    for (int off = 16; off > 0; off >>= 1)
        m = fminf(m, __shfl_xor_sync(0xffffffffu, m, off));

    const float S = g_rownorm[n];
    const float* xr = g_xt + (size_t)n * CDIM;
    float best = 1e30f; int bj = 0x7fffffff;
    #pragma unroll
    for (int q = 0; q < 8; q++) {
        if (ev[q] <= m + MARGIN) {
            int j = ei[q];
            const float* er = emb + (size_t)j * CDIM;
            float dot = 0.0f;
            #pragma unroll 8
            for (int k = 0; k < CDIM; k++)
                dot = __fmaf_rn(xr[k], er[k], dot);
            float d = __fadd_rn(S, -__fmul_rn(2.0f, dot));
            if (d < best || (d == best && j < bj)) { best = d; bj = j; }
        }
    }
    #pragma unroll
    for (int off = 16; off > 0; off >>= 1) {
        float ov = __shfl_xor_sync(0xffffffffu, best, off);
        int   oj = __shfl_xor_sync(0xffffffffu, bj,   off);
        if (ov < best || (ov == best && oj < bj)) { best = ov; bj = oj; }
    }
    if (lid == 0) {
        g_idx[n] = bj;
        idx_out_f[n] = (float)bj;
    }
}

// ---------------- K4: gather + straight-through output + loss partials --------
__global__ void k_output(const float* __restrict__ emb, float* __restrict__ out) {
    __shared__ float tile[32][33];
    __shared__ double sred[256];
    int b = blockIdx.z, c0 = blockIdx.y * 32, hw0 = blockIdx.x * 32;
    int tx = threadIdx.x, ty = threadIdx.y;        // (32, 8)
    double acc = 0.0;
    #pragma unroll
    for (int i = ty; i < 32; i += 8) {
        int n = b * HW + hw0 + i;
        int id = g_idx[n];
        float zv = g_xt[(size_t)n * CDIM + c0 + tx];
        float qv = emb[(size_t)id * CDIM + c0 + tx];
        float t  = __fsub_rn(qv, zv);
        float o  = __fadd_rn(zv, t);
        tile[i][tx] = o;
        acc += (double)__fmul_rn(t, t);
    }
    __syncthreads();
    #pragma unroll
    for (int i = ty; i < 32; i += 8)
        out[((size_t)(b * CDIM + c0 + i)) * HW + hw0 + tx] = tile[tx][i];

    int tid = ty * 32 + tx;
    sred[tid] = acc;
    __syncthreads();
    for (int s = 128; s > 0; s >>= 1) {
        if (tid < s) sred[tid] += sred[tid + s];
        __syncthreads();
    }
    if (tid == 0)
        g_partial[blockIdx.x + 32 * (blockIdx.y + 8 * blockIdx.z)] = sred[0];
}

// ---------------- K5: final loss reduce ----------------
__global__ void k_loss(float* __restrict__ out_loss) {
    __shared__ double sred[256];
    int tid = threadIdx.x;
    double acc = 0.0;
    for (int q = tid; q < 4096; q += 256) acc += g_partial[q];
    sred[tid] = acc;
    __syncthreads();
    for (int s = 128; s > 0; s >>= 1) {
        if (tid < s) sred[tid] += sred[tid + s];
        __syncthreads();
    }
    if (tid == 0) {
        float m = (float)(sred[0] / (double)OUT_N);
        out_loss[0] = __fadd_rn(m, __fmul_rn(0.25f, m));
    }
}

// ---------------- entry ----------------
extern "C" void kernel_launch(void* const* d_in, const int* in_sizes, int n_in,
                              void* d_out, int out_size) {
    const float* z   = (const float*)d_in[0];
    const float* emb = (const float*)d_in[1];
    float* out    = (float*)d_out;
    float* loss_p = out + OUT_N;
    float* idx_p  = out + OUT_N + 1;

    cudaFuncSetAttribute(k_gemm_coarse,
                         cudaFuncAttributeMaxDynamicSharedMemorySize, GEMM_SMEM);

    k_transpose<<<dim3(32, 8, 16), dim3(32, 8)>>>(z);
    k_rowprep<<<NROWS / 8, dim3(32, 8)>>>();
    k_eprep<<<KEMB / 8, dim3(32, 8)>>>(emb);
    k_gemm_coarse<<<dim3(NROWS / 128, KEMB / 128), 512, GEMM_SMEM>>>();
    k_rescore<<<NROWS / 4, 128>>>(emb, idx_p);
    k_output<<<dim3(32, 8, 16), dim3(32, 8)>>>(emb, out);
    k_loss<<<1, 256>>>(loss_p);
}

// round 9
// speedup vs baseline: 1.2036x; 1.2036x over previous
#include <cuda_runtime.h>
#include <cuda_bf16.h>
#include <cstdint>

#define NROWS 16384
#define CDIM  256
#define KEMB  8192
#define NBATCH 16
#define HW    1024
#define OUT_N (NBATCH * CDIM * HW)   // 4194304

#define NTILES 64                     // 8192 / 128 column tiles
#define MARGIN 4.0e-4f

#define APITCH 144                    // smem row pitch (bytes): 64 bf16 + 16B pad
#define ABUF   (128 * APITCH)         // 18432 B (A chunk: 128 rows x 64 bf16)
#define BBUF   (128 * APITCH)         // 18432 B (B chunk: 128 codewords x 64 bf16)
#define STAGE  (ABUF + BBUF)          // 36864 B
#define GEMM_SMEM (2 * STAGE)         // 73728 B -> 2 CTAs/SM
#define RPW 9                         // reduction smem pitch (words per row)

// ---------------- static device scratch ----------------
__device__ float          g_xt[NROWS * CDIM];    // z transposed [n][c] fp32
__device__ __nv_bfloat16  g_xh[NROWS * CDIM];    // bf16(x)
__device__ __nv_bfloat16  g_eh[KEMB * CDIM];     // bf16(emb)
__device__ float          g_rownorm[NROWS];
__device__ int            g_idx[NROWS];
__device__ double         g_partial[4096];
__device__ float4         g_tv[NROWS * NTILES];  // top-4 coarse (-2*dot) per (row,tile)
__device__ int4           g_ti[NROWS * NTILES];  // matching indices

// top-4 running insert, strict < (keeps earliest-seen on ties)
#define TOP4_INSERT(dv, j)                                                    \
    if ((dv) < v3) {                                                          \
        if ((dv) < v2) {                                                      \
            v3 = v2; i3 = i2;                                                 \
            if ((dv) < v1) {                                                  \
                v2 = v1; i2 = i1;                                             \
                if ((dv) < v0) { v1 = v0; i1 = i0; v0 = (dv); i0 = (j); }     \
                else           { v1 = (dv); i1 = (j); }                       \
            } else { v2 = (dv); i2 = (j); }                                   \
        } else { v3 = (dv); i3 = (j); }                                       \
    }

__device__ __forceinline__ uint32_t smem_u32(const void* p) {
    uint32_t a;
    asm("{ .reg .u64 t; cvta.to.shared.u64 t, %1; cvt.u32.u64 %0, t; }" : "=r"(a) : "l"(p));
    return a;
}
__device__ __forceinline__ void ldsm_x4(uint32_t& r0, uint32_t& r1, uint32_t& r2,
                                        uint32_t& r3, uint32_t addr) {
    asm volatile("ldmatrix.sync.aligned.m8n8.x4.shared.b16 {%0,%1,%2,%3}, [%4];"
                 : "=r"(r0), "=r"(r1), "=r"(r2), "=r"(r3) : "r"(addr));
}
#define CP16(dst, src) \
    asm volatile("cp.async.cg.shared.global [%0], [%1], 16;" :: "r"(dst), "l"(src))
#define CP_COMMIT() asm volatile("cp.async.commit_group;" ::: "memory")

#define MMA_BF16(cc, a, b0, b1)                                               \
    asm volatile(                                                             \
        "mma.sync.aligned.m16n8k16.row.col.f32.bf16.bf16.f32 "                \
        "{%0,%1,%2,%3}, {%4,%5,%6,%7}, {%8,%9}, {%0,%1,%2,%3};"               \
        : "+f"((cc)[0]), "+f"((cc)[1]), "+f"((cc)[2]), "+f"((cc)[3])          \
        : "r"((a)[0]), "r"((a)[1]), "r"((a)[2]), "r"((a)[3]),                 \
          "r"(b0), "r"(b1))

// ---------------- K0: transpose z[B,C,HW] -> g_xt / g_xh ----------------
__global__ void k_transpose(const float* __restrict__ z) {
    __shared__ float t[32][33];
    int b = blockIdx.z, c0 = blockIdx.y * 32, hw0 = blockIdx.x * 32;
    int tx = threadIdx.x, ty = threadIdx.y;        // (32, 8)
    #pragma unroll
    for (int i = ty; i < 32; i += 8)
        t[i][tx] = z[((size_t)(b * CDIM + c0 + i)) * HW + hw0 + tx];
    __syncthreads();
    #pragma unroll
    for (int i = ty; i < 32; i += 8) {
        float v = t[tx][i];
        size_t o = ((size_t)(b * HW + hw0 + i)) * CDIM + c0 + tx;
        g_xt[o] = v;
        g_xh[o] = __float2bfloat16(v);
    }
}

// ---------------- K0b: emb -> bf16 ----------------
__global__ void k_ebf(const float* __restrict__ emb) {
    int i = blockIdx.x * 256 + threadIdx.x;        // over KEMB*CDIM/4
    float4 v = reinterpret_cast<const float4*>(emb)[i];
    __nv_bfloat16* o = g_eh + (size_t)i * 4;
    o[0] = __float2bfloat16(v.x); o[1] = __float2bfloat16(v.y);
    o[2] = __float2bfloat16(v.z); o[3] = __float2bfloat16(v.w);
}

// ---------------- K1: |x|^2 per row ----------------
__global__ void k_rownorm() {
    int row  = blockIdx.x * 8 + threadIdx.y;       // (32, 8)
    int lane = threadIdx.x;
    const float* r = g_xt + (size_t)row * CDIM;
    double acc = 0.0;
    #pragma unroll
    for (int h = 0; h < 2; h++) {
        float4 v = *reinterpret_cast<const float4*>(&r[h * 128 + lane * 4]);
        acc += (double)__fmul_rn(v.x, v.x);
        acc += (double)__fmul_rn(v.y, v.y);
        acc += (double)__fmul_rn(v.z, v.z);
        acc += (double)__fmul_rn(v.w, v.w);
    }
    #pragma unroll
    for (int off = 16; off > 0; off >>= 1)
        acc += __shfl_down_sync(0xffffffffu, acc, off);
    if (lane == 0) g_rownorm[row] = (float)acc;
}

// ---------------- K2: coarse bf16 mma.sync GEMM + per-tile top-4 ----------------
// CTA: 128 rows x 128 cols. K=256 streamed as 4 chunks of 64, 2-stage cp.async
// double buffer. 256 thr = 8 warps (4m x 2n), warp tile 32x64 -> 192 B crossbar
// per MMA (was 256). 2 CTAs/SM.
__global__ __launch_bounds__(256, 2) void k_gemm_coarse() {
    extern __shared__ __align__(16) char smem[];
    const uint32_t sbase = smem_u32(smem);
    const int tid = threadIdx.x;
    const int rowBase = blockIdx.x * 128;
    const int colBase = blockIdx.y * 128;

    const char* Ag = (const char*)(g_xh + (size_t)rowBase * CDIM);
    const char* Bg = (const char*)(g_eh + (size_t)colBase * CDIM);

    // per-thread cp.async coords: 1024 16B transfers per operand per chunk
    const int ldr = tid >> 3, ldc = tid & 7;       // rows 0..31 (x4 via it), col16 0..7

    auto load_chunk = [&](int ch) {
        const uint32_t dA = sbase + (uint32_t)((ch & 1) * STAGE);
        const uint32_t dB = dA + ABUF;
        #pragma unroll
        for (int it = 0; it < 4; it++) {
            int r = ldr + it * 32;
            uint32_t so = (uint32_t)(r * APITCH + ldc * 16);
            size_t  go = ((size_t)r * CDIM + ch * 64 + ldc * 8) * 2;
            CP16(dA + so, Ag + go);
            CP16(dB + so, Bg + go);
        }
        CP_COMMIT();
    };

    const int lane = tid & 31, wid = tid >> 5;
    const int g = lane >> 2, m4 = lane & 3;
    const int mw = wid >> 1, nw = wid & 1;         // 4 m-groups x 2 n-groups

    float c[2][8][4];
    #pragma unroll
    for (int mt = 0; mt < 2; mt++)
        #pragma unroll
        for (int nt = 0; nt < 8; nt++)
            #pragma unroll
            for (int q = 0; q < 4; q++) c[mt][nt][q] = 0.0f;

    // ldmatrix per-lane offsets (within a stage)
    const uint32_t aoff = (uint32_t)((mw * 32 + (lane & 15)) * APITCH
                                     + ((lane >> 4) & 1) * 16);
    const uint32_t boff = (uint32_t)(ABUF
                                     + (nw * 64 + ((lane >> 4) & 1) * 8 + (lane & 7)) * APITCH
                                     + ((lane >> 3) & 1) * 16);

    auto compute_chunk = [&](int ch) {
        const uint32_t sg = sbase + (uint32_t)((ch & 1) * STAGE);
        const uint32_t bA = sg + aoff;
        const uint32_t bB = sg + boff;
        #pragma unroll
        for (int ks = 0; ks < 4; ks++) {
            const uint32_t ko = ks * 32;
            uint32_t a[2][4], b[4][4];
            ldsm_x4(a[0][0], a[0][1], a[0][2], a[0][3], bA + ko);
            ldsm_x4(a[1][0], a[1][1], a[1][2], a[1][3], bA + 16 * APITCH + ko);
            #pragma unroll
            for (int ntp = 0; ntp < 4; ntp++)
                ldsm_x4(b[ntp][0], b[ntp][1], b[ntp][2], b[ntp][3],
                        bB + ntp * 16 * APITCH + ko);
            #pragma unroll
            for (int mt = 0; mt < 2; mt++)
                #pragma unroll
                for (int ntp = 0; ntp < 4; ntp++) {
                    MMA_BF16(c[mt][ntp * 2],     a[mt], b[ntp][0], b[ntp][1]);
                    MMA_BF16(c[mt][ntp * 2 + 1], a[mt], b[ntp][2], b[ntp][3]);
                }
        }
    };

    // 2-stage pipeline over 4 K-chunks
    load_chunk(0);
    load_chunk(1);
    asm volatile("cp.async.wait_group 1;" ::: "memory");
    __syncthreads();
    compute_chunk(0);
    __syncthreads();
    load_chunk(2);
    asm volatile("cp.async.wait_group 1;" ::: "memory");
    __syncthreads();
    compute_chunk(1);
    __syncthreads();
    load_chunk(3);
    asm volatile("cp.async.wait_group 1;" ::: "memory");
    __syncthreads();
    compute_chunk(2);
    __syncthreads();
    asm volatile("cp.async.wait_group 0;" ::: "memory");
    __syncthreads();
    compute_chunk(3);
    __syncthreads();   // buffers dead; reuse smem for reduction

    float* redv = reinterpret_cast<float*>(smem);
    int*   redi = reinterpret_cast<int*>(smem) + 128 * RPW;

    // ---- register epilogue: per-thread top-4 per local row, quad merge ----
    // row = mw*32 + mt*16 + hf*8 + g ; col = colBase + nw*64 + nt*8 + m4*2 + e
    #pragma unroll
    for (int lr = 0; lr < 4; lr++) {
        const int mt = lr >> 1, hf = lr & 1;
        float v0 = 1e30f, v1 = 1e30f, v2 = 1e30f, v3 = 1e30f;
        int   i0 = 0,     i1 = 0,     i2 = 0,     i3 = 0;
        #pragma unroll
        for (int nt = 0; nt < 8; nt++)
            #pragma unroll
            for (int e = 0; e < 2; e++) {
                float dv = -2.0f * c[mt][nt][hf * 2 + e];
                int j = colBase + nw * 64 + nt * 8 + m4 * 2 + e;
                TOP4_INSERT(dv, j);
            }
        #pragma unroll
        for (int s = 1; s <= 2; s <<= 1) {
            float w0 = __shfl_xor_sync(0xffffffffu, v0, s);
            float w1 = __shfl_xor_sync(0xffffffffu, v1, s);
            float w2 = __shfl_xor_sync(0xffffffffu, v2, s);
            float w3 = __shfl_xor_sync(0xffffffffu, v3, s);
            int   q0 = __shfl_xor_sync(0xffffffffu, i0, s);
            int   q1 = __shfl_xor_sync(0xffffffffu, i1, s);
            int   q2 = __shfl_xor_sync(0xffffffffu, i2, s);
            int   q3 = __shfl_xor_sync(0xffffffffu, i3, s);
            TOP4_INSERT(w0, q0); TOP4_INSERT(w1, q1);
            TOP4_INSERT(w2, q2); TOP4_INSERT(w3, q3);
        }
        if (m4 == 0) {
            int row = mw * 32 + mt * 16 + hf * 8 + g;
            int base = row * RPW + nw * 4;
            redv[base + 0] = v0; redv[base + 1] = v1;
            redv[base + 2] = v2; redv[base + 3] = v3;
            redi[base + 0] = i0; redi[base + 1] = i1;
            redi[base + 2] = i2; redi[base + 3] = i3;
        }
    }
    __syncthreads();

    // ---- merge 2 warp-column ranges -> per-row top-4 over 128 cols ----
    if (tid < 128) {
        float v0 = 1e30f, v1 = 1e30f, v2 = 1e30f, v3 = 1e30f;
        int   i0 = 0,     i1 = 0,     i2 = 0,     i3 = 0;
        #pragma unroll
        for (int e = 0; e < 8; e++) {
            float dv = redv[tid * RPW + e];
            int j = redi[tid * RPW + e];
            TOP4_INSERT(dv, j);
        }
        int n = rowBase + tid;
        g_tv[(size_t)n * NTILES + blockIdx.y] = make_float4(v0, v1, v2, v3);
        g_ti[(size_t)n * NTILES + blockIdx.y] = make_int4(i0, i1, i2, i3);
    }
}

// ---------------- K3: exact rescore of near-min candidates ----------------
// One warp per row; 256 stored entries; rescore all within MARGIN of coarse min
// with the EXACT fp32 chain; lexicographic (d, j) = first-index tie-break.
__global__ __launch_bounds__(128) void k_rescore(const float* __restrict__ emb,
                                                 float* __restrict__ idx_out_f) {
    int wid = threadIdx.x >> 5, lid = threadIdx.x & 31;
    int n = blockIdx.x * 4 + wid;
    const float4* tv = g_tv + (size_t)n * NTILES;
    const int4*   ti = g_ti + (size_t)n * NTILES;

    float ev[8]; int ei[8];
    #pragma unroll
    for (int q = 0; q < 8; q++) {
        int e = q * 32 + lid;                      // entry 0..255
        float4 v4 = tv[e >> 2];
        int4   i4 = ti[e >> 2];
        int rk = e & 3;
        ev[q] = (rk == 0) ? v4.x : (rk == 1) ? v4.y : (rk == 2) ? v4.z : v4.w;
        ei[q] = (rk == 0) ? i4.x : (rk == 1) ? i4.y : (rk == 2) ? i4.z : i4.w;
    }
    float m = 1e30f;
    #pragma unroll
    for (int q = 0; q < 8; q++) m = fminf(m, ev[q]);
    #pragma unroll
    for (int off = 16; off > 0; off >>= 1)
        m = fminf(m, __shfl_xor_sync(0xffffffffu, m, off));

    const float S = g_rownorm[n];
    const float* xr = g_xt + (size_t)n * CDIM;
    float best = 1e30f; int bj = 0x7fffffff;
    #pragma unroll
    for (int q = 0; q < 8; q++) {
        if (ev[q] <= m + MARGIN) {
            int j = ei[q];
            const float* er = emb + (size_t)j * CDIM;
            float dot = 0.0f;
            #pragma unroll 8
            for (int k = 0; k < CDIM; k++)
                dot = __fmaf_rn(xr[k], er[k], dot);
            float d = __fadd_rn(S, -__fmul_rn(2.0f, dot));
            if (d < best || (d == best && j < bj)) { best = d; bj = j; }
        }
    }
    #pragma unroll
    for (int off = 16; off > 0; off >>= 1) {
        float ov = __shfl_xor_sync(0xffffffffu, best, off);
        int   oj = __shfl_xor_sync(0xffffffffu, bj,   off);
        if (ov < best || (ov == best && oj < bj)) { best = ov; bj = oj; }
    }
    if (lid == 0) {
        g_idx[n] = bj;
        idx_out_f[n] = (float)bj;
    }
}

// ---------------- K4: gather + straight-through output + loss partials --------
__global__ void k_output(const float* __restrict__ emb, float* __restrict__ out) {
    __shared__ float tile[32][33];
    __shared__ double sred[256];
    int b = blockIdx.z, c0 = blockIdx.y * 32, hw0 = blockIdx.x * 32;
    int tx = threadIdx.x, ty = threadIdx.y;        // (32, 8)
    double acc = 0.0;
    #pragma unroll
    for (int i = ty; i < 32; i += 8) {
        int n = b * HW + hw0 + i;
        int id = g_idx[n];
        float zv = g_xt[(size_t)n * CDIM + c0 + tx];
        float qv = emb[(size_t)id * CDIM + c0 + tx];
        float t  = __fsub_rn(qv, zv);
        float o  = __fadd_rn(zv, t);
        tile[i][tx] = o;
        acc += (double)__fmul_rn(t, t);
    }
    __syncthreads();
    #pragma unroll
    for (int i = ty; i < 32; i += 8)
        out[((size_t)(b * CDIM + c0 + i)) * HW + hw0 + tx] = tile[tx][i];

    int tid = ty * 32 + tx;
    sred[tid] = acc;
    __syncthreads();
    for (int s = 128; s > 0; s >>= 1) {
        if (tid < s) sred[tid] += sred[tid + s];
        __syncthreads();
    }
    if (tid == 0)
        g_partial[blockIdx.x + 32 * (blockIdx.y + 8 * blockIdx.z)] = sred[0];
}

// ---------------- K5: final loss reduce ----------------
__global__ void k_loss(float* __restrict__ out_loss) {
    __shared__ double sred[256];
    int tid = threadIdx.x;
    double acc = 0.0;
    for (int q = tid; q < 4096; q += 256) acc += g_partial[q];
    sred[tid] = acc;
    __syncthreads();
    for (int s = 128; s > 0; s >>= 1) {
        if (tid < s) sred[tid] += sred[tid + s];
        __syncthreads();
    }
    if (tid == 0) {
        float m = (float)(sred[0] / (double)OUT_N);
        out_loss[0] = __fadd_rn(m, __fmul_rn(0.25f, m));
    }
}

// ---------------- entry ----------------
extern "C" void kernel_launch(void* const* d_in, const int* in_sizes, int n_in,
                              void* d_out, int out_size) {
    const float* z   = (const float*)d_in[0];
    const float* emb = (const float*)d_in[1];
    float* out    = (float*)d_out;
    float* loss_p = out + OUT_N;
    float* idx_p  = out + OUT_N + 1;

    cudaFuncSetAttribute(k_gemm_coarse,
                         cudaFuncAttributeMaxDynamicSharedMemorySize, GEMM_SMEM);

    k_transpose<<<dim3(32, 8, 16), dim3(32, 8)>>>(z);
    k_ebf<<<(KEMB * CDIM / 4) / 256, 256>>>(emb);
    k_rownorm<<<NROWS / 8, dim3(32, 8)>>>();
    k_gemm_coarse<<<dim3(NROWS / 128, KEMB / 128), 256, GEMM_SMEM>>>();
    k_rescore<<<NROWS / 4, 128>>>(emb, idx_p);
    k_output<<<dim3(32, 8, 16), dim3(32, 8)>>>(emb, out);
    k_loss<<<1, 256>>>(loss_p);
}